// round 6
// baseline (speedup 1.0000x reference)
#include <cuda_runtime.h>
#include <cuda_fp16.h>
#include <cstdint>

#define BATCH 4
#define H 128
#define W 128
#define HW (H*W)
#define CIN_X 256
#define CSKIP 128
#define CCAT 384
#define NPAIR (CCAT/2)   // 192
#define COUT 128
#define NPAIR2 (COUT/2)  // 64
#define OPAD 32
#define NPIX (BATCH*HW)
#define EPSV 1e-5f
#define ASTR 72          // halves per smem row (144B)

#define NW1 (9*COUT*NPAIR)    // 221184
#define NW2 (9*COUT*NPAIR2)   // 73728
#define NW3 (9*OPAD*NPAIR2)   // 18432

// ---------------- scratch ------------------------------------------------------
__device__ __align__(16) __half   g_cat[(size_t)BATCH*HW*CCAT];    // ch-last fp16
__device__ __align__(16) __half2  g_wpT[NW1];                      // conv1 w [tap][oc][pair]
__device__ __align__(16) __half2  g_wp2T[NW2];                     // def w
__device__ __align__(16) __half2  g_wpoT[NW3];                     // off w (padded)
__device__ __align__(16) __half2  g_hraw[(size_t)BATCH*HW*NPAIR2]; // conv1 out, ch-last fp16
__device__ __align__(16) __half2  g_hh[(size_t)BATCH*HW*NPAIR2];   // BN1+ReLU h
__device__ float   g_off[BATCH*18*HW];
__device__ float   g_y[(size_t)BATCH*HW*COUT];
__device__ float g_sum1[COUT], g_sq1[COUT], g_sum2[COUT], g_sq2[COUT];
__device__ float g_scale1[COUT], g_shift1[COUT], g_scale2[COUT], g_shift2[COUT];

// ---------------- helpers ------------------------------------------------------
__device__ __forceinline__ void ldm_x4(uint32_t& r0, uint32_t& r1, uint32_t& r2,
                                       uint32_t& r3, uint32_t addr) {
    asm volatile("ldmatrix.sync.aligned.m8n8.x4.shared.b16 {%0,%1,%2,%3}, [%4];"
                 : "=r"(r0), "=r"(r1), "=r"(r2), "=r"(r3) : "r"(addr));
}
__device__ __forceinline__ void mma16816(float* c, const uint32_t* a, const uint32_t* b) {
    asm volatile(
        "mma.sync.aligned.m16n8k16.row.col.f32.f16.f16.f32 "
        "{%0,%1,%2,%3}, {%4,%5,%6,%7}, {%8,%9}, {%0,%1,%2,%3};"
        : "+f"(c[0]), "+f"(c[1]), "+f"(c[2]), "+f"(c[3])
        : "r"(a[0]), "r"(a[1]), "r"(a[2]), "r"(a[3]), "r"(b[0]), "r"(b[1]));
}
__device__ __forceinline__ void cp_async16(uint32_t dst, const void* src) {
    asm volatile("cp.async.cg.shared.global [%0], [%1], 16;"
                 :: "r"(dst), "l"(src) : "memory");
}
__device__ __forceinline__ void cp_async16s(uint32_t dst, const void* src, int ssize) {
    asm volatile("cp.async.cg.shared.global [%0], [%1], 16, %2;"
                 :: "r"(dst), "l"(src), "r"(ssize) : "memory");
}
#define CP_COMMIT() asm volatile("cp.async.commit_group;" ::: "memory")
#define CP_WAIT1()  asm volatile("cp.async.wait_group 1;" ::: "memory")
#define CP_WAIT0()  asm volatile("cp.async.wait_group 0;" ::: "memory")

// ---------------- kernel P: fused zero + weight packs ---------------------------
__global__ void k_prep(const float* __restrict__ cw, const float* __restrict__ dw,
                       const float* __restrict__ ow) {
    int idx = blockIdx.x * 256 + threadIdx.x;
    if (idx < COUT) { g_sum1[idx]=0.f; g_sq1[idx]=0.f; g_sum2[idx]=0.f; g_sq2[idx]=0.f; }
    if (idx < NW1) {
        int p   = idx % NPAIR;
        int oc  = (idx / NPAIR) % COUT;
        int tap = idx / (NPAIR*COUT);
        float w0 = cw[((size_t)oc*CCAT + 2*p    )*9 + tap];
        float w1 = cw[((size_t)oc*CCAT + 2*p + 1)*9 + tap];
        g_wpT[idx] = __floats2half2_rn(w0, w1);
    } else if (idx < NW1 + NW2) {
        int j = idx - NW1;
        int p   = j % NPAIR2;
        int oc  = (j / NPAIR2) % COUT;
        int tap = j / (NPAIR2*COUT);
        float w0 = dw[((size_t)oc*COUT + 2*p    )*9 + tap];
        float w1 = dw[((size_t)oc*COUT + 2*p + 1)*9 + tap];
        g_wp2T[j] = __floats2half2_rn(w0, w1);
    } else if (idx < NW1 + NW2 + NW3) {
        int j = idx - NW1 - NW2;
        int p   = j % NPAIR2;
        int oc  = (j / NPAIR2) % OPAD;
        int tap = j / (NPAIR2*OPAD);
        float w0 = 0.f, w1 = 0.f;
        if (oc < 18) {
            w0 = ow[((size_t)oc*COUT + 2*p    )*9 + tap];
            w1 = ow[((size_t)oc*COUT + 2*p + 1)*9 + tap];
        }
        g_wpoT[j] = __floats2half2_rn(w0, w1);
    }
}

// ---------------- kernel A: upsample + concat -> ch-last fp16 -------------------
__global__ void k_upcat(const float* __restrict__ x, const float* __restrict__ skip) {
    int idx = blockIdx.x * blockDim.x + threadIdx.x;
    if (idx >= BATCH*HW*(NPAIR/4)) return;
    int xc = idx % W;
    int y  = (idx / W) % H;
    int g4 = (idx / HW) % (NPAIR/4);
    int b  = idx / (HW*(NPAIR/4));
    int p0 = g4 * 4;
    __half2 res[4];
    if (p0 < CSKIP/2) {
        const float* sp = skip + ((size_t)(b*CSKIP + 2*p0)*HW) + y*W + xc;
        #pragma unroll
        for (int j = 0; j < 4; j++) {
            float v0 = sp[(size_t)(2*j  )*HW];
            float v1 = sp[(size_t)(2*j+1)*HW];
            res[j] = __floats2half2_rn(v0, v1);
        }
    } else {
        int ci0 = 2*p0 - CSKIP;
        float fy = (float)y  * (63.0f / 127.0f);
        float fx = (float)xc * (63.0f / 127.0f);
        int y0 = (int)fy, x0 = (int)fx;
        float wy = fy - (float)y0, wx = fx - (float)x0;
        int y1 = min(y0+1, 63), x1 = min(x0+1, 63);
        int i00 = y0*64+x0, i01 = y0*64+x1, i10 = y1*64+x0, i11 = y1*64+x1;
        float w00 = (1.f-wy)*(1.f-wx), w01 = (1.f-wy)*wx;
        float w10 = wy*(1.f-wx), w11 = wy*wx;
        const float* xp = x + (size_t)(b*CIN_X + ci0)*4096;
        #pragma unroll
        for (int j = 0; j < 4; j++) {
            const float* c0p = xp + (size_t)(2*j)*4096;
            const float* c1p = c0p + 4096;
            float v0 = c0p[i00]*w00 + c0p[i01]*w01 + c0p[i10]*w10 + c0p[i11]*w11;
            float v1 = c1p[i00]*w00 + c1p[i01]*w01 + c1p[i10]*w10 + c1p[i11]*w11;
            res[j] = __floats2half2_rn(v0, v1);
        }
    }
    // channels-last write: pixel base + p0*2 halves (16B aligned)
    *(uint4*)&g_cat[((size_t)(b*HW + y*W + xc))*CCAT + p0*2] = *(uint4*)res;
}

// ---------------- kernel B: conv1 mma, ch-last cp.async, double-buffered --------
#define ABUF_BYTES (128*ASTR*2)   // 18432
#define CONV1_SMEM (4*ABUF_BYTES + COUT*2*4)
__global__ __launch_bounds__(256) void k_conv1_mma() {
    extern __shared__ __align__(16) unsigned char dynsmem[];
    uint32_t smemU = (uint32_t)__cvta_generic_to_shared(dynsmem);
    uint32_t aBuf0 = smemU;
    uint32_t aBuf1 = smemU + ABUF_BYTES;
    uint32_t bBuf0 = smemU + 2*ABUF_BYTES;
    uint32_t bBuf1 = smemU + 3*ABUF_BYTES;
    float* sS = (float*)(dynsmem + 4*ABUF_BYTES);
    float* sQ = sS + COUT;

    int tid = threadIdx.x;
    int wid = tid >> 5, lane = tid & 31;
    int tileX = blockIdx.x * 32, tileY = blockIdx.y * 4;
    int b = blockIdx.z;
    int mBase = (wid & 1) * 64;
    int nBase = (wid >> 1) * 32;
    int grp = lane >> 2, tig = lane & 3;

    uint32_t aOff = (uint32_t)(((mBase + (lane & 15))*ASTR + (lane >> 4)*8) * 2);
    uint32_t bOff = (uint32_t)(((nBase + (lane & 7) + ((lane >> 4) & 1)*8)*ASTR
                                + ((lane >> 3) & 1)*8) * 2);

    float acc[4][4][4];
    #pragma unroll
    for (int mi=0;mi<4;mi++)
        #pragma unroll
        for (int ni=0;ni<4;ni++)
            #pragma unroll
            for (int r=0;r<4;r++) acc[mi][ni][r]=0.f;

    int px_s = tid & 127;
    int half_s = tid >> 7;
    int ly_s = px_s >> 5, lx_s = px_s & 31;
    int ocb = tid >> 3, segb = tid & 7;

    auto prefetch = [&](int t, uint32_t aB, uint32_t bB) {
        int tap = t / 6, c = t - tap*6;
        int ky = tap/3 - 1, kx = tap - (tap/3)*3 - 1;
        int gy = tileY + ly_s + ky, gx = tileX + lx_s + kx;
        bool valid = (gy >= 0) && (gy < H) && (gx >= 0) && (gx < W);
        int ssz = valid ? 16 : 0;
        const __half* asrc = g_cat + ((size_t)(b*HW + (valid ? gy*W + gx : 0)))*CCAT
                             + c*64 + half_s*32;
        uint32_t adst = aB + (uint32_t)((px_s*ASTR + half_s*32) * 2);
        #pragma unroll
        for (int j = 0; j < 4; j++)
            cp_async16s(adst + j*16, asrc + j*8, ssz);
        const __half2* bsrc = g_wpT + (size_t)tap*COUT*NPAIR + c*32;
        #pragma unroll
        for (int j = 0; j < 4; j++) {
            int oc = ocb + j*32;
            cp_async16(bB + (uint32_t)((oc*ASTR + segb*8) * 2),
                       bsrc + (size_t)oc*NPAIR + segb*4);
        }
    };

    prefetch(0, aBuf0, bBuf0);
    CP_COMMIT();

    for (int t = 0; t < 54; t++) {
        uint32_t aB = (t & 1) ? aBuf1 : aBuf0;
        uint32_t bB = (t & 1) ? bBuf1 : bBuf0;
        if (t < 53) {
            uint32_t aN = (t & 1) ? aBuf0 : aBuf1;
            uint32_t bN = (t & 1) ? bBuf0 : bBuf1;
            prefetch(t+1, aN, bN);
            CP_COMMIT();
            CP_WAIT1();
        } else {
            CP_WAIT0();
        }
        __syncthreads();
        #pragma unroll
        for (int ks = 0; ks < 4; ks++) {
            uint32_t af[4][4], bf[4][2];
            #pragma unroll
            for (int mi = 0; mi < 4; mi++)
                ldm_x4(af[mi][0], af[mi][1], af[mi][2], af[mi][3],
                       aB + aOff + mi*(16*ASTR*2) + ks*32);
            ldm_x4(bf[0][0], bf[0][1], bf[1][0], bf[1][1], bB + bOff + ks*32);
            ldm_x4(bf[2][0], bf[2][1], bf[3][0], bf[3][1],
                   bB + bOff + 16*ASTR*2 + ks*32);
            #pragma unroll
            for (int mi = 0; mi < 4; mi++)
                #pragma unroll
                for (int ni = 0; ni < 4; ni++)
                    mma16816(acc[mi][ni], af[mi], bf[ni]);
        }
        __syncthreads();
    }

    if (tid < COUT) { sS[tid] = 0.f; sQ[tid] = 0.f; }
    __syncthreads();
    #pragma unroll
    for (int ni = 0; ni < 4; ni++) {
        int oc = nBase + ni*8 + tig*2;
        float s0=0.f,q0=0.f,s1=0.f,q1=0.f;
        #pragma unroll
        for (int mi = 0; mi < 4; mi++) {
            int px0 = mBase + mi*16 + grp;
            int px1 = px0 + 8;
            size_t gp0 = ((size_t)b*HW + (tileY + (px0>>5))*W + tileX + (px0&31))*NPAIR2;
            size_t gp1 = ((size_t)b*HW + (tileY + (px1>>5))*W + tileX + (px1&31))*NPAIR2;
            float a0 = acc[mi][ni][0], a1 = acc[mi][ni][1];
            float a2 = acc[mi][ni][2], a3 = acc[mi][ni][3];
            g_hraw[gp0 + (oc>>1)] = __floats2half2_rn(a0, a1);
            g_hraw[gp1 + (oc>>1)] = __floats2half2_rn(a2, a3);
            s0 += a0 + a2; q0 += a0*a0 + a2*a2;
            s1 += a1 + a3; q1 += a1*a1 + a3*a3;
        }
        atomicAdd(&sS[oc], s0);   atomicAdd(&sQ[oc], q0);
        atomicAdd(&sS[oc+1], s1); atomicAdd(&sQ[oc+1], q1);
    }
    __syncthreads();
    if (tid < COUT) {
        atomicAdd(&g_sum1[tid], sS[tid]);
        atomicAdd(&g_sq1[tid], sQ[tid]);
    }
}

// ---------------- kernel C: finalize BN ------------------------------------------
__global__ void k_bnfin(int which, const float* __restrict__ g, const float* __restrict__ bb) {
    int c = threadIdx.x;
    if (c >= COUT) return;
    float s = which ? g_sum2[c] : g_sum1[c];
    float q = which ? g_sq2[c]  : g_sq1[c];
    float m = s / (float)NPIX;
    float v = q / (float)NPIX - m*m;
    float sc = g[c] * rsqrtf(v + EPSV);
    float sh = bb[c] - m * sc;
    if (which) { g_scale2[c] = sc; g_shift2[c] = sh; }
    else       { g_scale1[c] = sc; g_shift1[c] = sh; }
}

// ---------------- kernel D: BN1+ReLU fp16 -> fp16 ---------------------------------
__global__ void k_bnrelu1() {
    int idx = blockIdx.x * 256 + threadIdx.x;
    if (idx >= BATCH*HW*16) return;
    uint4 q = ((const uint4*)g_hraw)[idx];
    int p0 = (idx & 15) * 4;
    uint32_t* e = (uint32_t*)&q;
    uint4 o;
    uint32_t* oe = (uint32_t*)&o;
    #pragma unroll
    for (int j = 0; j < 4; j++) {
        float2 f = __half22float2(*(__half2*)&e[j]);
        int c = 2*(p0 + j);
        float r0 = fmaxf(f.x * g_scale1[c]   + g_shift1[c],   0.f);
        float r1 = fmaxf(f.y * g_scale1[c+1] + g_shift1[c+1], 0.f);
        __half2 hv = __floats2half2_rn(r0, r1);
        oe[j] = *(uint32_t*)&hv;
    }
    ((uint4*)g_hh)[idx] = o;
}

// ---------------- kernel E: offset conv via mma ------------------------------------
__global__ __launch_bounds__(256) void k_offconv_mma(const float* __restrict__ bias) {
    __shared__ __align__(16) __half sA[2][128*ASTR];
    __shared__ __align__(16) __half sB[2][OPAD*ASTR];
    int tid = threadIdx.x;
    int wid = tid >> 5, lane = tid & 31;
    int tileX = blockIdx.x * 32, tileY = blockIdx.y * 4;
    int b = blockIdx.z;
    int mBase = (wid & 3) * 32;
    int nBase = (wid >> 2) * 16;
    int grp = lane >> 2, tig = lane & 3;

    uint32_t sA_u = (uint32_t)__cvta_generic_to_shared(sA);
    uint32_t sB_u = (uint32_t)__cvta_generic_to_shared(sB);
    uint32_t aOff = (uint32_t)(((mBase + (lane & 15))*ASTR + (lane >> 4)*8) * 2);
    uint32_t bOff = (uint32_t)(((nBase + (lane & 7) + ((lane >> 4) & 1)*8)*ASTR
                                + ((lane >> 3) & 1)*8) * 2);

    float acc[2][2][4];
    #pragma unroll
    for (int mi=0;mi<2;mi++)
        #pragma unroll
        for (int ni=0;ni<2;ni++)
            #pragma unroll
            for (int r=0;r<4;r++) acc[mi][ni][r]=0.f;

    int px_s = tid & 127;
    int half_s = tid >> 7;
    int ly_s = px_s >> 5, lx_s = px_s & 31;
    int ocb = tid >> 3, segb = tid & 7;

    auto prefetch = [&](int t, int buf) {
        int tap = t >> 1, ch = t & 1;
        int pb = ch * 32;
        int ky = tap/3 - 1, kx = tap - (tap/3)*3 - 1;
        int gy = tileY + ly_s + ky, gx = tileX + lx_s + kx;
        bool valid = (gy >= 0) && (gy < H) && (gx >= 0) && (gx < W);
        int ssz = valid ? 16 : 0;
        const __half2* asrc = g_hh + ((size_t)b*HW + (valid ? gy*W + gx : 0))*NPAIR2
                              + pb + half_s*16;
        uint32_t adst = sA_u + buf*(uint32_t)(128*ASTR*2)
                        + (uint32_t)((px_s*ASTR + half_s*32) * 2);
        #pragma unroll
        for (int jj = 0; jj < 4; jj++)
            cp_async16s(adst + jj*16, asrc + jj*4, ssz);
        const __half2* bsrc = g_wpoT + (size_t)tap*OPAD*NPAIR2 + (size_t)ocb*NPAIR2
                              + pb + segb*4;
        cp_async16(sB_u + buf*(uint32_t)(OPAD*ASTR*2)
                   + (uint32_t)((ocb*ASTR + segb*8) * 2), bsrc);
    };

    prefetch(0, 0);
    CP_COMMIT();
    for (int t = 0; t < 18; t++) {
        int buf = t & 1;
        if (t < 17) { prefetch(t+1, buf^1); CP_COMMIT(); CP_WAIT1(); }
        else CP_WAIT0();
        __syncthreads();
        uint32_t aB = sA_u + buf*(uint32_t)(128*ASTR*2);
        uint32_t bB = sB_u + buf*(uint32_t)(OPAD*ASTR*2);
        #pragma unroll
        for (int ks = 0; ks < 4; ks++) {
            uint32_t af[2][4], bf[2][2];
            #pragma unroll
            for (int mi = 0; mi < 2; mi++)
                ldm_x4(af[mi][0], af[mi][1], af[mi][2], af[mi][3],
                       aB + aOff + mi*(16*ASTR*2) + ks*32);
            ldm_x4(bf[0][0], bf[0][1], bf[1][0], bf[1][1], bB + bOff + ks*32);
            #pragma unroll
            for (int mi = 0; mi < 2; mi++)
                #pragma unroll
                for (int ni = 0; ni < 2; ni++)
                    mma16816(acc[mi][ni], af[mi], bf[ni]);
        }
        __syncthreads();
    }

    #pragma unroll
    for (int ni = 0; ni < 2; ni++) {
        int oc = nBase + ni*8 + tig*2;
        if (oc >= 18) continue;
        float b0 = bias[oc];
        float b1 = (oc + 1 < 18) ? bias[oc+1] : 0.f;
        #pragma unroll
        for (int mi = 0; mi < 2; mi++) {
            int px0 = mBase + mi*16 + grp;
            int px1 = px0 + 8;
            int y0 = tileY + (px0>>5), x0 = tileX + (px0&31);
            int y1 = tileY + (px1>>5), x1 = tileX + (px1&31);
            g_off[((size_t)(b*18 + oc)*HW) + y0*W + x0] = acc[mi][ni][0] + b0;
            g_off[((size_t)(b*18 + oc)*HW) + y1*W + x1] = acc[mi][ni][2] + b0;
            if (oc + 1 < 18) {
                g_off[((size_t)(b*18 + oc + 1)*HW) + y0*W + x0] = acc[mi][ni][1] + b1;
                g_off[((size_t)(b*18 + oc + 1)*HW) + y1*W + x1] = acc[mi][ni][3] + b1;
            }
        }
    }
}

// ---------------- kernel F: deformable conv, smem halo gather + mma ---------------
#define D_HALO  0
#define D_SA    36864
#define D_SB    55296
#define D_OFFG  73728
#define D_WGT   75776
#define D_HOF   77824
#define D_OK    79872
#define D_SS    80384
#define D_SQ    80896
#define DEF_SMEM 81408
__global__ __launch_bounds__(256) void k_deform_mma(const float* __restrict__ db) {
    extern __shared__ __align__(16) unsigned char dyn[];
    __half* halo = (__half*)(dyn + D_HALO);
    int*   sOffG = (int*)(dyn + D_OFFG);
    float* sWgt  = (float*)(dyn + D_WGT);
    int*   sHOf  = (int*)(dyn + D_HOF);
    int*   sOK   = (int*)(dyn + D_OK);
    float* sS    = (float*)(dyn + D_SS);
    float* sQ    = (float*)(dyn + D_SQ);
    uint32_t smemU = (uint32_t)__cvta_generic_to_shared(dyn);
    uint32_t haloU = smemU + D_HALO;
    uint32_t sA_u  = smemU + D_SA;
    uint32_t sB_u  = smemU + D_SB;
    __half* sA = (__half*)(dyn + D_SA);

    int tid = threadIdx.x;
    int wid = tid >> 5, lane = tid & 31;
    int tileX = blockIdx.x * 32, tileY = blockIdx.y * 4;
    int b = blockIdx.z;
    int mBase = (wid & 1) * 64;
    int nBase = (wid >> 1) * 32;
    int grp = lane >> 2, tig = lane & 3;
    int hY0 = tileY - 2, hX0 = tileX - 2;

    uint32_t aAddr = sA_u + (uint32_t)(((mBase + (lane & 15))*ASTR + (lane >> 4)*8) * 2);
    uint32_t bAddr = sB_u + (uint32_t)(((nBase + (lane & 7) + ((lane >> 4) & 1)*8)*ASTR
                                        + ((lane >> 3) & 1)*8) * 2);

    float acc[4][4][4];
    #pragma unroll
    for (int mi=0;mi<4;mi++)
        #pragma unroll
        for (int ni=0;ni<4;ni++)
            #pragma unroll
            for (int r=0;r<4;r++) acc[mi][ni][r]=0.f;

    int px_s = tid & 127;
    int half_s = tid >> 7;
    int ocb = tid >> 3, segb = tid & 7;

    for (int c0 = 0; c0 < COUT; c0 += 64) {
        // ---- load halo (8 rows x 36 cols x 64 ch) once per chunk ----
        for (int i = tid; i < 288*8; i += 256) {
            int px_h = i >> 3, seg = i & 7;
            int yr = min(max(hY0 + px_h/36, 0), H-1);
            int xr = min(max(hX0 + px_h%36, 0), W-1);
            const __half2* src = g_hh + ((size_t)(b*HW + yr*W + xr))*NPAIR2
                                 + (c0>>1) + seg*4;
            cp_async16(haloU + (uint32_t)(px_h*128 + seg*16), src);
        }
        CP_COMMIT(); CP_WAIT0();
        __syncthreads();

        for (int tap = 0; tap < 9; tap++) {
            if (tid < 128) {
                int ly = tid >> 5, lx = tid & 31;
                int y = tileY + ly, x = tileX + lx;
                float dy = g_off[((size_t)(b*18 + 2*tap    )*HW) + y*W + x];
                float dx = g_off[((size_t)(b*18 + 2*tap + 1)*HW) + y*W + x];
                float py = (float)y + (float)(tap/3 - 1) + dy;
                float pxx = (float)x + (float)(tap%3 - 1) + dx;
                float y0f = floorf(py), x0f = floorf(pxx);
                float wy = py - y0f, wx = pxx - x0f;
                int yi = (int)y0f, xi = (int)x0f;
                bool yv0 = (yi >= 0) && (yi < H);
                bool yv1 = (yi+1 >= 0) && (yi+1 < H);
                bool xv0 = (xi >= 0) && (xi < W);
                bool xv1 = (xi+1 >= 0) && (xi+1 < W);
                int yc0 = min(max(yi, 0), H-1), yc1 = min(max(yi+1, 0), H-1);
                int xc0 = min(max(xi, 0), W-1), xc1 = min(max(xi+1, 0), W-1);
                int base = b*HW;
                sOffG[0*128+tid] = (base + yc0*W + xc0) * NPAIR2;
                sOffG[1*128+tid] = (base + yc0*W + xc1) * NPAIR2;
                sOffG[2*128+tid] = (base + yc1*W + xc0) * NPAIR2;
                sOffG[3*128+tid] = (base + yc1*W + xc1) * NPAIR2;
                sWgt[0*128+tid] = (yv0 && xv0) ? (1.f-wy)*(1.f-wx) : 0.f;
                sWgt[1*128+tid] = (yv0 && xv1) ? (1.f-wy)*wx       : 0.f;
                sWgt[2*128+tid] = (yv1 && xv0) ? wy*(1.f-wx)       : 0.f;
                sWgt[3*128+tid] = (yv1 && xv1) ? wy*wx             : 0.f;
                int ry0 = yc0 - hY0, ry1 = yc1 - hY0;
                int rx0 = xc0 - hX0, rx1 = xc1 - hX0;
                sHOf[0*128+tid] = (ry0*36 + rx0) * 128;
                sHOf[1*128+tid] = (ry0*36 + rx1) * 128;
                sHOf[2*128+tid] = (ry1*36 + rx0) * 128;
                sHOf[3*128+tid] = (ry1*36 + rx1) * 128;
                sOK[tid] = (ry0 >= 0) && (ry1 < 8) && (rx0 >= 0) && (rx1 < 36);
            }
            __syncthreads();

            // B prefetch for this (tap, c0)
            const __half2* bsrc = g_wp2T + (size_t)tap*COUT*NPAIR2 + (c0 >> 1);
            #pragma unroll
            for (int j = 0; j < 4; j++) {
                int oc = ocb + j*32;
                cp_async16(sB_u + (uint32_t)((oc*ASTR + segb*8) * 2),
                           bsrc + (size_t)oc*NPAIR2 + segb*4);
            }
            CP_COMMIT();

            float w0 = sWgt[0*128+px_s], w1 = sWgt[1*128+px_s];
            float w2 = sWgt[2*128+px_s], w3 = sWgt[3*128+px_s];
            const uint4 *p0, *p1, *p2, *p3;
            if (sOK[px_s]) {
                const char* hb = (const char*)halo;
                p0 = (const uint4*)(hb + sHOf[0*128+px_s] + half_s*64);
                p1 = (const uint4*)(hb + sHOf[1*128+px_s] + half_s*64);
                p2 = (const uint4*)(hb + sHOf[2*128+px_s] + half_s*64);
                p3 = (const uint4*)(hb + sHOf[3*128+px_s] + half_s*64);
            } else {
                int pb = (c0 >> 1) + half_s*16;
                p0 = (const uint4*)(g_hh + sOffG[0*128+px_s] + pb);
                p1 = (const uint4*)(g_hh + sOffG[1*128+px_s] + pb);
                p2 = (const uint4*)(g_hh + sOffG[2*128+px_s] + pb);
                p3 = (const uint4*)(g_hh + sOffG[3*128+px_s] + pb);
            }
            #pragma unroll
            for (int j = 0; j < 4; j++) {
                uint4 q0 = p0[j], q1 = p1[j], q2 = p2[j], q3 = p3[j];
                uint32_t res[4];
                const uint32_t* a0 = (const uint32_t*)&q0;
                const uint32_t* a1 = (const uint32_t*)&q1;
                const uint32_t* a2 = (const uint32_t*)&q2;
                const uint32_t* a3 = (const uint32_t*)&q3;
                #pragma unroll
                for (int e = 0; e < 4; e++) {
                    float2 f0 = __half22float2(*(__half2*)&a0[e]);
                    float2 f1 = __half22float2(*(__half2*)&a1[e]);
                    float2 f2 = __half22float2(*(__half2*)&a2[e]);
                    float2 f3 = __half22float2(*(__half2*)&a3[e]);
                    float rx = w0*f0.x + w1*f1.x + w2*f2.x + w3*f3.x;
                    float ry = w0*f0.y + w1*f1.y + w2*f2.y + w3*f3.y;
                    __half2 hv = __floats2half2_rn(rx, ry);
                    res[e] = *(uint32_t*)&hv;
                }
                *(uint4*)&sA[px_s*ASTR + half_s*32 + j*8] = *(uint4*)res;
            }
            CP_WAIT0();
            __syncthreads();
            #pragma unroll
            for (int ks = 0; ks < 4; ks++) {
                uint32_t af[4][4], bf[4][2];
                #pragma unroll
                for (int mi = 0; mi < 4; mi++)
                    ldm_x4(af[mi][0], af[mi][1], af[mi][2], af[mi][3],
                           aAddr + mi*(16*ASTR*2) + ks*32);
                ldm_x4(bf[0][0], bf[0][1], bf[1][0], bf[1][1], bAddr + ks*32);
                ldm_x4(bf[2][0], bf[2][1], bf[3][0], bf[3][1],
                       bAddr + 16*ASTR*2 + ks*32);
                #pragma unroll
                for (int mi = 0; mi < 4; mi++)
                    #pragma unroll
                    for (int ni = 0; ni < 4; ni++)
                        mma16816(acc[mi][ni], af[mi], bf[ni]);
            }
            __syncthreads();
        }
    }

    if (tid < COUT) { sS[tid] = 0.f; sQ[tid] = 0.f; }
    __syncthreads();
    #pragma unroll
    for (int ni = 0; ni < 4; ni++) {
        int oc = nBase + ni*8 + tig*2;
        float b0 = db[oc], b1 = db[oc+1];
        float s0=0.f,q0=0.f,s1=0.f,q1=0.f;
        #pragma unroll
        for (int mi = 0; mi < 4; mi++) {
            int px0 = mBase + mi*16 + grp;
            int px1 = px0 + 8;
            size_t gp0 = ((size_t)b*HW + (tileY + (px0>>5))*W + tileX + (px0&31))*COUT;
            size_t gp1 = ((size_t)b*HW + (tileY + (px1>>5))*W + tileX + (px1&31))*COUT;
            float a0 = acc[mi][ni][0] + b0, a1 = acc[mi][ni][1] + b1;
            float a2 = acc[mi][ni][2] + b0, a3 = acc[mi][ni][3] + b1;
            *(float2*)&g_y[gp0 + oc] = make_float2(a0, a1);
            *(float2*)&g_y[gp1 + oc] = make_float2(a2, a3);
            s0 += a0 + a2; q0 += a0*a0 + a2*a2;
            s1 += a1 + a3; q1 += a1*a1 + a3*a3;
        }
        atomicAdd(&sS[oc], s0);   atomicAdd(&sQ[oc], q0);
        atomicAdd(&sS[oc+1], s1); atomicAdd(&sQ[oc+1], q1);
    }
    __syncthreads();
    if (tid < COUT) {
        atomicAdd(&g_sum2[tid], sS[tid]);
        atomicAdd(&g_sq2[tid], sQ[tid]);
    }
}

// ---------------- kernel H: BN2+ReLU ch-last -> planar out ------------------------
__global__ __launch_bounds__(256) void k_bnrelu2(float* __restrict__ out) {
    __shared__ float s[32][129];
    int tid = threadIdx.x;
    int px0 = blockIdx.x * 32;
    int b = blockIdx.y;
    #pragma unroll
    for (int j = 0; j < 16; j++) {
        int idx = tid + j*256;
        int pxl = idx >> 7, c = idx & 127;
        s[pxl][c] = g_y[((size_t)b*HW + px0 + pxl)*COUT + c];
    }
    __syncthreads();
    #pragma unroll
    for (int j = 0; j < 16; j++) {
        int idx = tid + j*256;
        int c = idx >> 5, pxl = idx & 31;
        float v = s[pxl][c] * g_scale2[c] + g_shift2[c];
        out[((size_t)(b*COUT + c)*HW) + px0 + pxl] = fmaxf(v, 0.f);
    }
}

// ---------------- launch -----------------------------------------------------------
extern "C" void kernel_launch(void* const* d_in, const int* in_sizes, int n_in,
                              void* d_out, int out_size) {
    const float* x       = (const float*)d_in[0];
    const float* skip    = (const float*)d_in[1];
    const float* conv1_w = (const float*)d_in[2];
    const float* bn1_g   = (const float*)d_in[3];
    const float* bn1_b   = (const float*)d_in[4];
    const float* off_w   = (const float*)d_in[5];
    const float* off_b   = (const float*)d_in[6];
    const float* def_w   = (const float*)d_in[7];
    const float* def_b   = (const float*)d_in[8];
    const float* bn2_g   = (const float*)d_in[9];
    const float* bn2_b   = (const float*)d_in[10];
    float* out = (float*)d_out;

    static bool attrDone = false;
    if (!attrDone) {
        cudaFuncSetAttribute(k_conv1_mma,
                             cudaFuncAttributeMaxDynamicSharedMemorySize, CONV1_SMEM);
        cudaFuncSetAttribute(k_deform_mma,
                             cudaFuncAttributeMaxDynamicSharedMemorySize, DEF_SMEM);
        attrDone = true;
    }

    int nprep = NW1 + NW2 + NW3;
    k_prep<<<(nprep + 255)/256, 256>>>(conv1_w, def_w, off_w);

    int nup = BATCH*HW*(NPAIR/4);
    k_upcat<<<(nup + 255)/256, 256>>>(x, skip);

    k_conv1_mma<<<dim3(W/32, H/4, BATCH), 256, CONV1_SMEM>>>();
    k_bnfin<<<1, COUT>>>(0, bn1_g, bn1_b);

    int nhp = BATCH*HW*16;
    k_bnrelu1<<<(nhp + 255)/256, 256>>>();

    k_offconv_mma<<<dim3(W/32, H/4, BATCH), 256>>>(off_b);

    k_deform_mma<<<dim3(W/32, H/4, BATCH), 256, DEF_SMEM>>>(def_b);
    k_bnfin<<<1, COUT>>>(1, bn2_g, bn2_b);

    k_bnrelu2<<<dim3(HW/32, BATCH), 256>>>(out);
}